// round 2
// baseline (speedup 1.0000x reference)
#include <cuda_runtime.h>
#include <cuda_bf16.h>
#include <math.h>

// ---------------------------------------------------------------------------
// Problem constants
//   x   [8,2048,1024]   A [256,256]   Bm [256,1024]  C [1024,256] D [1024,1024]
//   ln_w/ln_b [1024]    W1 [4096,1024] b1 [4096]     W2 [1024,4096] b2 [1024]
//   out = y [8,2048,1024] ++ final_state [8,256]
// ---------------------------------------------------------------------------
#define BSZ   8
#define TLEN  2048
#define HID   1024
#define STATE 256
#define FFNDIM 4096
#define MROWS (BSZ*TLEN)          // 16384

// Scratch (device globals: allocation-free rule)
__device__ float g_xB[MROWS*STATE];      //  16 MB  [b*T+t, s]
__device__ float g_xD[MROWS*HID];        //  64 MB  [b*T+t, h]  (reused as pre-LN r)
__device__ float g_states[MROWS*STATE];  //  16 MB
__device__ float g_yln[MROWS*HID];       //  64 MB
__device__ float g_h[MROWS*FFNDIM];      // 256 MB

__device__ __forceinline__ float gelu_exact(float v) {
    return 0.5f * v * (1.0f + erff(v * 0.70710678118654752f));
}

// ---------------------------------------------------------------------------
// Generic fp32 GEMM:  C[M,N] = A[M,K] @ B[N,K]^T  (+bias[n]) (gelu) (+add1) (+add2)
// Tiles: 128x128x8, 256 threads, 8x8 per thread (4x4 quads at offsets 0/64).
// All of M,N,K here are multiples of the tile dims (16384 / {256,1024,4096} / {256,1024,4096}).
// ---------------------------------------------------------------------------
__global__ void __launch_bounds__(256, 2) gemm_nt_kernel(
    const float* __restrict__ A, const float* __restrict__ B, float* Cmat,
    int M, int N, int K,
    const float* __restrict__ bias, const float* add1, const float* add2,
    int do_gelu)
{
    __shared__ float As[8][128];
    __shared__ float Bs[8][128];

    const int tid  = threadIdx.x;
    const int row0 = blockIdx.y * 128;
    const int col0 = blockIdx.x * 128;

    // cooperative tile loads: thread -> one float4 of A-tile and B-tile
    const int lrow = tid >> 1;           // 0..127
    const int lcol = (tid & 1) << 2;     // 0 or 4

    const float* Ap = A + (size_t)(row0 + lrow) * K + lcol;
    const float* Bp = B + (size_t)(col0 + lrow) * K + lcol;

    const int tx = tid & 15;
    const int ty = tid >> 4;
    const int mA = ty * 4;               // row quads at mA and 64+mA
    const int nB = tx * 4;               // col quads at nB and 64+nB

    float acc[8][8];
#pragma unroll
    for (int i = 0; i < 8; ++i)
#pragma unroll
        for (int j = 0; j < 8; ++j) acc[i][j] = 0.f;

    float4 a4 = *(const float4*)Ap;
    float4 b4 = *(const float4*)Bp;

    const int ktiles = K >> 3;
    for (int kt = 0; kt < ktiles; ++kt) {
        As[lcol + 0][lrow] = a4.x; As[lcol + 1][lrow] = a4.y;
        As[lcol + 2][lrow] = a4.z; As[lcol + 3][lrow] = a4.w;
        Bs[lcol + 0][lrow] = b4.x; Bs[lcol + 1][lrow] = b4.y;
        Bs[lcol + 2][lrow] = b4.z; Bs[lcol + 3][lrow] = b4.w;
        __syncthreads();
        if (kt + 1 < ktiles) {
            a4 = *(const float4*)(Ap + (size_t)(kt + 1) * 8);
            b4 = *(const float4*)(Bp + (size_t)(kt + 1) * 8);
        }
#pragma unroll
        for (int k = 0; k < 8; ++k) {
            float a0[4], a1[4], b0[4], b1[4];
            *(float4*)a0 = *(const float4*)&As[k][mA];
            *(float4*)a1 = *(const float4*)&As[k][64 + mA];
            *(float4*)b0 = *(const float4*)&Bs[k][nB];
            *(float4*)b1 = *(const float4*)&Bs[k][64 + nB];
#pragma unroll
            for (int i = 0; i < 4; ++i)
#pragma unroll
                for (int j = 0; j < 4; ++j) {
                    acc[i][j]         += a0[i] * b0[j];
                    acc[i][j + 4]     += a0[i] * b1[j];
                    acc[i + 4][j]     += a1[i] * b0[j];
                    acc[i + 4][j + 4] += a1[i] * b1[j];
                }
        }
        __syncthreads();
    }

    // epilogue
#pragma unroll
    for (int i = 0; i < 8; ++i) {
        int r = row0 + ((i < 4) ? (mA + i) : (64 + mA + (i - 4)));
        size_t rowbase = (size_t)r * N;
#pragma unroll
        for (int jh = 0; jh < 2; ++jh) {
            int gc = col0 + ((jh == 0) ? nB : (64 + nB));
            size_t idx = rowbase + gc;
            float4 v;
            v.x = acc[i][jh * 4 + 0]; v.y = acc[i][jh * 4 + 1];
            v.z = acc[i][jh * 4 + 2]; v.w = acc[i][jh * 4 + 3];
            if (bias) {
                float4 bb = *(const float4*)(bias + gc);
                v.x += bb.x; v.y += bb.y; v.z += bb.z; v.w += bb.w;
            }
            if (do_gelu) {
                v.x = gelu_exact(v.x); v.y = gelu_exact(v.y);
                v.z = gelu_exact(v.z); v.w = gelu_exact(v.w);
            }
            if (add1) {
                float4 t = *(const float4*)(add1 + idx);
                v.x += t.x; v.y += t.y; v.z += t.z; v.w += t.w;
            }
            if (add2) {
                float4 t = *(const float4*)(add2 + idx);
                v.x += t.x; v.y += t.y; v.z += t.z; v.w += t.w;
            }
            *(float4*)(Cmat + idx) = v;
        }
    }
}

// ---------------------------------------------------------------------------
// Sequential scan: one block per batch (8 blocks x 1024 threads).
//   state = tanh(state @ A^T + xB[t]);  states[t] = state
// Thread (i = tid>>2, j = tid&3) owns k-range [64j, 64j+64) of output row i:
//   first 32 A coeffs in registers, last 32 in padded SMEM (conflict-free).
// State in SMEM (double-sync per step), xB prefetched one step ahead.
// ---------------------------------------------------------------------------
#define SCAN_A2_FLOATS (1024 * 33)
#define SCAN_SMEM_BYTES ((SCAN_A2_FLOATS + STATE + 2 * STATE) * 4)

__global__ void __launch_bounds__(1024, 1) scan_kernel(
    const float* __restrict__ Amat,
    const float* __restrict__ xB,
    float* __restrict__ states,
    float* __restrict__ fs_out)
{
    extern __shared__ float sm[];
    float* A2 = sm;                        // [1024][33] padded
    float* st = sm + SCAN_A2_FLOATS;       // [256]   (16B aligned)
    float* xb = st + STATE;                // [2][256]

    const int b   = blockIdx.x;
    const int tid = threadIdx.x;
    const int i   = tid >> 2;
    const int j   = tid & 3;

    const float* arow = Amat + i * STATE + j * 64;
    float areg[32];
#pragma unroll
    for (int c = 0; c < 32; ++c) areg[c] = arow[c];
    float* a2p = A2 + tid * 33;
#pragma unroll
    for (int c = 0; c < 32; ++c) a2p[c] = arow[32 + c];

    const float* xbbase = xB + (size_t)b * TLEN * STATE;
    float* sbptr = states + (size_t)b * TLEN * STATE;

    if (tid < STATE) {
        st[tid] = 0.f;
        xb[tid] = xbbase[tid];
    }
    __syncthreads();

    for (int t = 0; t < TLEN; ++t) {
        float pref = 0.f;
        if (tid < STATE && t + 1 < TLEN)
            pref = xbbase[(size_t)(t + 1) * STATE + tid];

        const float* sp = st + j * 64;
        float sum = 0.f;
#pragma unroll
        for (int c = 0; c < 32; c += 4) {
            float4 s4 = *(const float4*)(sp + c);
            sum += areg[c] * s4.x + areg[c + 1] * s4.y +
                   areg[c + 2] * s4.z + areg[c + 3] * s4.w;
        }
#pragma unroll
        for (int c = 0; c < 32; c += 4) {
            float4 s4 = *(const float4*)(sp + 32 + c);
            sum += a2p[c] * s4.x + a2p[c + 1] * s4.y +
                   a2p[c + 2] * s4.z + a2p[c + 3] * s4.w;
        }
        sum += __shfl_xor_sync(0xffffffffu, sum, 1);
        sum += __shfl_xor_sync(0xffffffffu, sum, 2);

        const int cur = t & 1;
        float ns = 0.f;
        if (j == 0) ns = tanhf(sum + xb[cur * STATE + i]);
        __syncthreads();                       // all reads of st done
        if (j == 0) {
            st[i] = ns;
            sbptr[(size_t)t * STATE + i] = ns;
        }
        if (tid < STATE && t + 1 < TLEN)
            xb[(cur ^ 1) * STATE + tid] = pref;
        __syncthreads();
    }

    if (fs_out != nullptr && tid < STATE)
        fs_out[b * STATE + tid] = st[tid];
}

// ---------------------------------------------------------------------------
// LayerNorm over last dim (1024). One block per row, 256 threads x float4.
// ---------------------------------------------------------------------------
__global__ void __launch_bounds__(256) ln_kernel(
    const float* __restrict__ R, const float* __restrict__ w,
    const float* __restrict__ b, float* __restrict__ Y)
{
    const int row = blockIdx.x;
    const int tid = threadIdx.x;
    const float4 v = ((const float4*)(R + (size_t)row * HID))[tid];

    float s  = v.x + v.y + v.z + v.w;
    float sq = v.x * v.x + v.y * v.y + v.z * v.z + v.w * v.w;
#pragma unroll
    for (int o = 16; o; o >>= 1) {
        s  += __shfl_xor_sync(0xffffffffu, s, o);
        sq += __shfl_xor_sync(0xffffffffu, sq, o);
    }
    __shared__ float ss[8], sqq[8], mv[2];
    const int wid = tid >> 5, lane = tid & 31;
    if (lane == 0) { ss[wid] = s; sqq[wid] = sq; }
    __syncthreads();
    if (tid == 0) {
        float S = 0.f, Q = 0.f;
#pragma unroll
        for (int k = 0; k < 8; ++k) { S += ss[k]; Q += sqq[k]; }
        float mu  = S * (1.0f / HID);
        float var = Q * (1.0f / HID) - mu * mu;
        mv[0] = mu;
        mv[1] = rsqrtf(var + 1e-5f);
    }
    __syncthreads();
    const float mu = mv[0], inv = mv[1];
    const float4 w4 = ((const float4*)w)[tid];
    const float4 b4 = ((const float4*)b)[tid];
    float4 o;
    o.x = (v.x - mu) * inv * w4.x + b4.x;
    o.y = (v.y - mu) * inv * w4.y + b4.y;
    o.z = (v.z - mu) * inv * w4.z + b4.z;
    o.w = (v.w - mu) * inv * w4.w + b4.w;
    ((float4*)(Y + (size_t)row * HID))[tid] = o;
}

// ---------------------------------------------------------------------------
// Launch
// ---------------------------------------------------------------------------
extern "C" void kernel_launch(void* const* d_in, const int* in_sizes, int n_in,
                              void* d_out, int out_size)
{
    const float* x    = (const float*)d_in[0];
    const float* Amat = (const float*)d_in[1];
    const float* Bm   = (const float*)d_in[2];
    const float* Cm   = (const float*)d_in[3];
    const float* D    = (const float*)d_in[4];
    const float* ln_w = (const float*)d_in[5];
    const float* ln_b = (const float*)d_in[6];
    const float* W1   = (const float*)d_in[7];
    const float* b1   = (const float*)d_in[8];
    const float* W2   = (const float*)d_in[9];
    const float* b2   = (const float*)d_in[10];
    float* out = (float*)d_out;

    float *xB, *xD, *states, *yln, *h;
    cudaGetSymbolAddress((void**)&xB,     g_xB);
    cudaGetSymbolAddress((void**)&xD,     g_xD);
    cudaGetSymbolAddress((void**)&states, g_states);
    cudaGetSymbolAddress((void**)&yln,    g_yln);
    cudaGetSymbolAddress((void**)&h,      g_h);

    cudaFuncSetAttribute(scan_kernel,
                         cudaFuncAttributeMaxDynamicSharedMemorySize,
                         SCAN_SMEM_BYTES);

    dim3 blk(256);
    const int M = MROWS;

    // 1) xB = x @ Bm^T     [16384,256]
    gemm_nt_kernel<<<dim3(STATE / 128, M / 128), blk>>>(
        x, Bm, xB, M, STATE, HID, nullptr, nullptr, nullptr, 0);

    // 2) xD = x @ D^T      [16384,1024]
    gemm_nt_kernel<<<dim3(HID / 128, M / 128), blk>>>(
        x, D, xD, M, HID, HID, nullptr, nullptr, nullptr, 0);

    // 3) sequential scan -> states (+ final_state into tail of d_out)
    float* fsp = (out_size >= MROWS * HID + BSZ * STATE)
                     ? (out + (size_t)MROWS * HID) : nullptr;
    scan_kernel<<<BSZ, 1024, SCAN_SMEM_BYTES>>>(Amat, xB, states, fsp);

    // 4) r = states @ C^T + xD + x   (in-place into xD; each elem read/written
    //    by the same thread)
    gemm_nt_kernel<<<dim3(HID / 128, M / 128), blk>>>(
        states, Cm, xD, M, HID, STATE, nullptr, xD, x, 0);

    // 5) yln = LayerNorm(r)
    ln_kernel<<<M, 256>>>(xD, ln_w, ln_b, yln);

    // 6) h = gelu(yln @ W1^T + b1)   [16384,4096]
    gemm_nt_kernel<<<dim3(FFNDIM / 128, M / 128), blk>>>(
        yln, W1, h, M, FFNDIM, HID, b1, nullptr, nullptr, 1);

    // 7) y = yln + h @ W2^T + b2 -> d_out
    gemm_nt_kernel<<<dim3(HID / 128, M / 128), blk>>>(
        h, W2, out, M, HID, FFNDIM, b2, yln, nullptr, 0);
}

// round 4
// speedup vs baseline: 1.3227x; 1.3227x over previous
#include <cuda_runtime.h>
#include <cuda_fp16.h>
#include <math.h>
#include <stdint.h>

// ---------------------------------------------------------------------------
// Problem constants
//   x [8,2048,1024]  A [256,256]  Bm [256,1024]  C [1024,256]  D [1024,1024]
//   ln_w/ln_b [1024] W1 [4096,1024] b1 [4096]  W2 [1024,4096] b2 [1024]
//   out = y [8,2048,1024] ++ final_state [8,256]
// ---------------------------------------------------------------------------
#define BSZ    8
#define TLEN   2048
#define HID    1024
#define STATE  256
#define FFNDIM 4096
#define MROWS  (BSZ*TLEN)          // 16384

// Scratch (device globals: allocation-free rule)
__device__ float g_xB[MROWS*STATE];      //  16 MB
__device__ float g_xD[MROWS*HID];        //  64 MB (reused as pre-LN r)
__device__ float g_states[MROWS*STATE];  //  16 MB
__device__ float g_yln[MROWS*HID];       //  64 MB
__device__ float g_h[MROWS*FFNDIM];      // 256 MB

__device__ __forceinline__ float gelu_exact(float v) {
    return 0.5f * v * (1.0f + erff(v * 0.70710678118654752f));
}

__device__ __forceinline__ uint32_t smem_u32(const void* p) {
    uint32_t a;
    asm("{ .reg .u64 t; cvta.to.shared.u64 t, %1; cvt.u32.u64 %0, t; }"
        : "=r"(a) : "l"(p));
    return a;
}

__device__ __forceinline__ void ldsm4(uint32_t addr, uint32_t r[4]) {
    asm volatile("ldmatrix.sync.aligned.m8n8.x4.shared.b16 {%0,%1,%2,%3}, [%4];"
                 : "=r"(r[0]), "=r"(r[1]), "=r"(r[2]), "=r"(r[3]) : "r"(addr));
}

__device__ __forceinline__ void mma16816(float c[4], const uint32_t a[4],
                                         uint32_t b0, uint32_t b1) {
    asm volatile(
        "mma.sync.aligned.m16n8k16.row.col.f32.f16.f16.f32 "
        "{%0,%1,%2,%3}, {%4,%5,%6,%7}, {%8,%9}, {%0,%1,%2,%3};"
        : "+f"(c[0]), "+f"(c[1]), "+f"(c[2]), "+f"(c[3])
        : "r"(a[0]), "r"(a[1]), "r"(a[2]), "r"(a[3]), "r"(b0), "r"(b1));
}

// ---------------------------------------------------------------------------
// fp16-split (3-pass) tensor-core GEMM:
//   C[M,N] = A[M,K] @ B[N,K]^T  (+bias[n]) (gelu) (+add1) (+add2)
// Block tile 128x128, 8 warps of 32x64, K-chunks of 32, double-buffered SMEM.
// SMEM rows have 80-byte stride (40 halfs): row*80 mod 128 cycles through all
// eight 16B offsets over 8 consecutive rows -> conflict-free ldmatrix.
// ---------------------------------------------------------------------------
#define GH_STRIDE_B 80                      // bytes per smem row (32 halfs + pad)
#define GH_TILE_B   (128 * GH_STRIDE_B)     // 10240
#define GH_AB 0
#define GH_AS (1 * GH_TILE_B)
#define GH_BB (2 * GH_TILE_B)
#define GH_BS (3 * GH_TILE_B)
#define GH_STAGE (4 * GH_TILE_B)            // 40960
#define GH_DYN_SMEM (2 * GH_STAGE)          // 81920

__global__ void __launch_bounds__(256, 1) gemm_h3_kernel(
    const float* __restrict__ A, const float* __restrict__ B,
    float* __restrict__ Cmat,
    int M, int N, int K,
    const float* __restrict__ bias, const float* __restrict__ add1,
    const float* __restrict__ add2, int do_gelu)
{
    extern __shared__ char smem[];
    const uint32_t sbase = smem_u32(smem);

    const int tid = threadIdx.x;
    const int w   = tid >> 5;
    const int l   = tid & 31;

    const size_t row0 = (size_t)blockIdx.y * 128;
    const size_t col0 = (size_t)blockIdx.x * 128;
    const int Kc = K >> 5;

    // ---- producer mapping: thread loads 4 float4 of A and 4 of B per chunk
    const int rbase = tid >> 3;          // 0..31, rows rbase+32*i
    const int c4    = tid & 7;           // k-offset c4*4
    const float* Ap = A + (row0 + rbase) * (size_t)K + c4 * 4;
    const float* Bp = B + (col0 + rbase) * (size_t)K + c4 * 4;

    float4 ra[4], rb4[4];
#pragma unroll
    for (int i = 0; i < 4; ++i) {
        ra[i]  = *(const float4*)(Ap + (size_t)(32 * i) * K);
        rb4[i] = *(const float4*)(Bp + (size_t)(32 * i) * K);
    }

    // convert+store lambda-equivalent (macro-ish via function scope)
    const uint32_t stoff = (uint32_t)rbase * GH_STRIDE_B + (uint32_t)c4 * 8;

#define CVST(sidx)                                                             \
    do {                                                                       \
        char* pAb = smem + (sidx) * GH_STAGE + GH_AB;                          \
        char* pAs = smem + (sidx) * GH_STAGE + GH_AS;                          \
        char* pBb = smem + (sidx) * GH_STAGE + GH_BB;                          \
        char* pBs = smem + (sidx) * GH_STAGE + GH_BS;                          \
        _Pragma("unroll")                                                      \
        for (int i = 0; i < 4; ++i) {                                          \
            uint32_t off = stoff + (uint32_t)i * (32u * GH_STRIDE_B);          \
            union { __half2 h2[2]; uint2 u; } pk;                              \
            __half2 hb0 = __floats2half2_rn(ra[i].x, ra[i].y);                 \
            __half2 hb1 = __floats2half2_rn(ra[i].z, ra[i].w);                 \
            float2 f0 = __half22float2(hb0), f1 = __half22float2(hb1);         \
            pk.h2[0] = hb0; pk.h2[1] = hb1;                                    \
            *(uint2*)(pAb + off) = pk.u;                                       \
            pk.h2[0] = __floats2half2_rn(ra[i].x - f0.x, ra[i].y - f0.y);      \
            pk.h2[1] = __floats2half2_rn(ra[i].z - f1.x, ra[i].w - f1.y);      \
            *(uint2*)(pAs + off) = pk.u;                                       \
            hb0 = __floats2half2_rn(rb4[i].x, rb4[i].y);                       \
            hb1 = __floats2half2_rn(rb4[i].z, rb4[i].w);                       \
            f0 = __half22float2(hb0); f1 = __half22float2(hb1);                \
            pk.h2[0] = hb0; pk.h2[1] = hb1;                                    \
            *(uint2*)(pBb + off) = pk.u;                                       \
            pk.h2[0] = __floats2half2_rn(rb4[i].x - f0.x, rb4[i].y - f0.y);    \
            pk.h2[1] = __floats2half2_rn(rb4[i].z - f1.x, rb4[i].w - f1.y);    \
            *(uint2*)(pBs + off) = pk.u;                                       \
        }                                                                      \
    } while (0)

    CVST(0);
    __syncthreads();

    // ---- warp tile mapping
    const int m0 = (w & 3) * 32;
    const int n0 = (w >> 2) * 64;
    // ldmatrix lane address components
    const int rA = l & 15;
    const int qA = l >> 4;
    const int rB = (l & 7) | ((l & 16) >> 1);
    const int qB = (l >> 3) & 1;

    float acc[2][8][4];
#pragma unroll
    for (int mi = 0; mi < 2; ++mi)
#pragma unroll
        for (int ni = 0; ni < 8; ++ni)
#pragma unroll
            for (int q = 0; q < 4; ++q) acc[mi][ni][q] = 0.f;

    for (int kt = 0; kt < Kc; ++kt) {
        // prefetch next chunk from GMEM
        if (kt + 1 < Kc) {
            const float* Ap2 = Ap + (kt + 1) * 32;
            const float* Bp2 = Bp + (kt + 1) * 32;
#pragma unroll
            for (int i = 0; i < 4; ++i) {
                ra[i]  = *(const float4*)(Ap2 + (size_t)(32 * i) * K);
                rb4[i] = *(const float4*)(Bp2 + (size_t)(32 * i) * K);
            }
        }

        const uint32_t stb = sbase + (uint32_t)(kt & 1) * GH_STAGE;
#pragma unroll
        for (int kk = 0; kk < 2; ++kk) {
            const int q0 = kk * 2;
            uint32_t ab[2][4], as2[2][4], bb[4][4];
            const uint32_t aoff =
                (uint32_t)(m0 + rA) * GH_STRIDE_B + (uint32_t)(q0 + qA) * 16;
            const uint32_t boff =
                (uint32_t)(n0 + rB) * GH_STRIDE_B + (uint32_t)(q0 + qB) * 16;

            ldsm4(stb + GH_AB + aoff, ab[0]);
            ldsm4(stb + GH_AB + aoff + 16u * GH_STRIDE_B, ab[1]);
            ldsm4(stb + GH_AS + aoff, as2[0]);
            ldsm4(stb + GH_AS + aoff + 16u * GH_STRIDE_B, as2[1]);
#pragma unroll
            for (int g = 0; g < 4; ++g)
                ldsm4(stb + GH_BB + boff + (uint32_t)g * (16u * GH_STRIDE_B), bb[g]);

            // pass 1: Ab * Bb
#pragma unroll
            for (int mi = 0; mi < 2; ++mi)
#pragma unroll
                for (int g = 0; g < 4; ++g) {
                    mma16816(acc[mi][2 * g],     ab[mi], bb[g][0], bb[g][1]);
                    mma16816(acc[mi][2 * g + 1], ab[mi], bb[g][2], bb[g][3]);
                }
            // pass 2: As * Bb
#pragma unroll
            for (int mi = 0; mi < 2; ++mi)
#pragma unroll
                for (int g = 0; g < 4; ++g) {
                    mma16816(acc[mi][2 * g],     as2[mi], bb[g][0], bb[g][1]);
                    mma16816(acc[mi][2 * g + 1], as2[mi], bb[g][2], bb[g][3]);
                }
            // pass 3: Ab * Bs (reload bb regs from Bs tile)
#pragma unroll
            for (int g = 0; g < 4; ++g)
                ldsm4(stb + GH_BS + boff + (uint32_t)g * (16u * GH_STRIDE_B), bb[g]);
#pragma unroll
            for (int mi = 0; mi < 2; ++mi)
#pragma unroll
                for (int g = 0; g < 4; ++g) {
                    mma16816(acc[mi][2 * g],     ab[mi], bb[g][0], bb[g][1]);
                    mma16816(acc[mi][2 * g + 1], ab[mi], bb[g][2], bb[g][3]);
                }
        }

        if (kt + 1 < Kc) CVST((kt + 1) & 1);
        __syncthreads();
    }
#undef CVST

    // ---- epilogue: acc is in registers; fused bias/gelu/residuals
#pragma unroll
    for (int mi = 0; mi < 2; ++mi) {
        const size_t rtop = row0 + m0 + mi * 16 + (l >> 2);
#pragma unroll
        for (int ni = 0; ni < 8; ++ni) {
            const int gc = (int)col0 + n0 + ni * 8 + (l & 3) * 2;
            float bx = 0.f, by = 0.f;
            if (bias) {
                float2 bb2 = *(const float2*)(bias + gc);
                bx = bb2.x; by = bb2.y;
            }
#pragma unroll
            for (int h = 0; h < 2; ++h) {
                const size_t r = rtop + h * 8;
                float vx = acc[mi][ni][h * 2 + 0] + bx;
                float vy = acc[mi][ni][h * 2 + 1] + by;
                if (do_gelu) { vx = gelu_exact(vx); vy = gelu_exact(vy); }
                const size_t idx = r * (size_t)N + gc;
                if (add1) {
                    float2 t = *(const float2*)(add1 + idx);
                    vx += t.x; vy += t.y;
                }
                if (add2) {
                    float2 t = *(const float2*)(add2 + idx);
                    vx += t.x; vy += t.y;
                }
                float2 o; o.x = vx; o.y = vy;
                *(float2*)(Cmat + idx) = o;
            }
        }
    }
}

// ---------------------------------------------------------------------------
// Sequential scan: one block per batch (8 blocks x 1024 threads).
// ---------------------------------------------------------------------------
#define SCAN_A2_FLOATS (1024 * 33)
#define SCAN_SMEM_BYTES ((SCAN_A2_FLOATS + STATE + 2 * STATE) * 4)

__global__ void __launch_bounds__(1024, 1) scan_kernel(
    const float* __restrict__ Amat,
    const float* __restrict__ xB,
    float* __restrict__ states,
    float* __restrict__ fs_out)
{
    extern __shared__ float sm[];
    float* A2 = sm;
    float* st = sm + SCAN_A2_FLOATS;
    float* xb = st + STATE;

    const int b   = blockIdx.x;
    const int tid = threadIdx.x;
    const int i   = tid >> 2;
    const int j   = tid & 3;

    const float* arow = Amat + i * STATE + j * 64;
    float areg[32];
#pragma unroll
    for (int c = 0; c < 32; ++c) areg[c] = arow[c];
    float* a2p = A2 + tid * 33;
#pragma unroll
    for (int c = 0; c < 32; ++c) a2p[c] = arow[32 + c];

    const float* xbbase = xB + (size_t)b * TLEN * STATE;
    float* sbptr = states + (size_t)b * TLEN * STATE;

    if (tid < STATE) {
        st[tid] = 0.f;
        xb[tid] = xbbase[tid];
    }
    __syncthreads();

    for (int t = 0; t < TLEN; ++t) {
        float pref = 0.f;
        if (tid < STATE && t + 1 < TLEN)
            pref = xbbase[(size_t)(t + 1) * STATE + tid];

        const float* sp = st + j * 64;
        float sum = 0.f;
#pragma unroll
        for (int c = 0; c < 32; c += 4) {
            float4 s4 = *(const float4*)(sp + c);
            sum += areg[c] * s4.x + areg[c + 1] * s4.y +
                   areg[c + 2] * s4.z + areg[c + 3] * s4.w;
        }
#pragma unroll
        for (int c = 0; c < 32; c += 4) {
            float4 s4 = *(const float4*)(sp + 32 + c);
            sum += a2p[c] * s4.x + a2p[c + 1] * s4.y +
                   a2p[c + 2] * s4.z + a2p[c + 3] * s4.w;
        }
        sum += __shfl_xor_sync(0xffffffffu, sum, 1);
        sum += __shfl_xor_sync(0xffffffffu, sum, 2);

        const int cur = t & 1;
        float ns = 0.f;
        if (j == 0) ns = tanhf(sum + xb[cur * STATE + i]);
        __syncthreads();
        if (j == 0) {
            st[i] = ns;
            sbptr[(size_t)t * STATE + i] = ns;
        }
        if (tid < STATE && t + 1 < TLEN)
            xb[(cur ^ 1) * STATE + tid] = pref;
        __syncthreads();
    }

    if (fs_out != nullptr && tid < STATE)
        fs_out[b * STATE + tid] = st[tid];
}

// ---------------------------------------------------------------------------
// LayerNorm over last dim (1024). One block per row, 256 threads x float4.
// ---------------------------------------------------------------------------
__global__ void __launch_bounds__(256) ln_kernel(
    const float* __restrict__ R, const float* __restrict__ w,
    const float* __restrict__ b, float* __restrict__ Y)
{
    const int row = blockIdx.x;
    const int tid = threadIdx.x;
    const float4 v = ((const float4*)(R + (size_t)row * HID))[tid];

    float s  = v.x + v.y + v.z + v.w;
    float sq = v.x * v.x + v.y * v.y + v.z * v.z + v.w * v.w;
#pragma unroll
    for (int o = 16; o; o >>= 1) {
        s  += __shfl_xor_sync(0xffffffffu, s, o);
        sq += __shfl_xor_sync(0xffffffffu, sq, o);
    }
    __shared__ float ss[8], sqq[8], mv[2];
    const int wid = tid >> 5, lane = tid & 31;
    if (lane == 0) { ss[wid] = s; sqq[wid] = sq; }
    __syncthreads();
    if (tid == 0) {
        float S = 0.f, Q = 0.f;
#pragma unroll
        for (int k = 0; k < 8; ++k) { S += ss[k]; Q += sqq[k]; }
        float mu  = S * (1.0f / HID);
        float var = Q * (1.0f / HID) - mu * mu;
        mv[0] = mu;
        mv[1] = rsqrtf(var + 1e-5f);
    }
    __syncthreads();
    const float mu = mv[0], inv = mv[1];
    const float4 w4 = ((const float4*)w)[tid];
    const float4 b4 = ((const float4*)b)[tid];
    float4 o;
    o.x = (v.x - mu) * inv * w4.x + b4.x;
    o.y = (v.y - mu) * inv * w4.y + b4.y;
    o.z = (v.z - mu) * inv * w4.z + b4.z;
    o.w = (v.w - mu) * inv * w4.w + b4.w;
    ((float4*)(Y + (size_t)row * HID))[tid] = o;
}

// ---------------------------------------------------------------------------
// Launch
// ---------------------------------------------------------------------------
extern "C" void kernel_launch(void* const* d_in, const int* in_sizes, int n_in,
                              void* d_out, int out_size)
{
    const float* x    = (const float*)d_in[0];
    const float* Amat = (const float*)d_in[1];
    const float* Bm   = (const float*)d_in[2];
    const float* Cm   = (const float*)d_in[3];
    const float* D    = (const float*)d_in[4];
    const float* ln_w = (const float*)d_in[5];
    const float* ln_b = (const float*)d_in[6];
    const float* W1   = (const float*)d_in[7];
    const float* b1   = (const float*)d_in[8];
    const float* W2   = (const float*)d_in[9];
    const float* b2   = (const float*)d_in[10];
    float* out = (float*)d_out;

    float *xB, *xD, *states, *yln, *h;
    cudaGetSymbolAddress((void**)&xB,     g_xB);
    cudaGetSymbolAddress((void**)&xD,     g_xD);
    cudaGetSymbolAddress((void**)&states, g_states);
    cudaGetSymbolAddress((void**)&yln,    g_yln);
    cudaGetSymbolAddress((void**)&h,      g_h);

    cudaFuncSetAttribute(scan_kernel,
                         cudaFuncAttributeMaxDynamicSharedMemorySize,
                         SCAN_SMEM_BYTES);
    cudaFuncSetAttribute(gemm_h3_kernel,
                         cudaFuncAttributeMaxDynamicSharedMemorySize,
                         GH_DYN_SMEM);

    const int M = MROWS;

    // 1) xB = x @ Bm^T
    gemm_h3_kernel<<<dim3(STATE / 128, M / 128), 256, GH_DYN_SMEM>>>(
        x, Bm, xB, M, STATE, HID, nullptr, nullptr, nullptr, 0);

    // 2) xD = x @ D^T
    gemm_h3_kernel<<<dim3(HID / 128, M / 128), 256, GH_DYN_SMEM>>>(
        x, D, xD, M, HID, HID, nullptr, nullptr, nullptr, 0);

    // 3) sequential scan -> states (+ final_state into tail of d_out)
    float* fsp = (out_size >= MROWS * HID + BSZ * STATE)
                     ? (out + (size_t)MROWS * HID) : nullptr;
    scan_kernel<<<BSZ, 1024, SCAN_SMEM_BYTES>>>(Amat, xB, states, fsp);

    // 4) r = states @ C^T + xD + x  (in-place into xD)
    gemm_h3_kernel<<<dim3(HID / 128, M / 128), 256, GH_DYN_SMEM>>>(
        states, Cm, xD, M, HID, STATE, nullptr, xD, x, 0);

    // 5) yln = LayerNorm(r)
    ln_kernel<<<M, 256>>>(xD, ln_w, ln_b, yln);

    // 6) h = gelu(yln @ W1^T + b1)
    gemm_h3_kernel<<<dim3(FFNDIM / 128, M / 128), 256, GH_DYN_SMEM>>>(
        yln, W1, h, M, FFNDIM, HID, b1, nullptr, nullptr, 1);

    // 7) y = yln + h @ W2^T + b2 -> d_out
    gemm_h3_kernel<<<dim3(HID / 128, M / 128), 256, GH_DYN_SMEM>>>(
        h, W2, out, M, HID, FFNDIM, b2, yln, nullptr, 0);
}

// round 5
// speedup vs baseline: 3.0661x; 2.3181x over previous
#include <cuda_runtime.h>
#include <cuda_fp16.h>
#include <math.h>
#include <stdint.h>

// ---------------------------------------------------------------------------
// Problem constants
//   x [8,2048,1024]  A [256,256]  Bm [256,1024]  C [1024,256]  D [1024,1024]
//   ln_w/ln_b [1024] W1 [4096,1024] b1 [4096]  W2 [1024,4096] b2 [1024]
//   out = y [8,2048,1024] ++ final_state [8,256]
// ---------------------------------------------------------------------------
#define BSZ    8
#define TLEN   2048
#define HID    1024
#define STATE  256
#define FFNDIM 4096
#define MROWS  (BSZ*TLEN)          // 16384

// Scratch (device globals: allocation-free rule)
__device__ float g_xB[MROWS*STATE];      //  16 MB
__device__ float g_xD[MROWS*HID];        //  64 MB (reused as pre-LN r)
__device__ float g_states[MROWS*STATE];  //  16 MB
__device__ float g_yln[MROWS*HID];       //  64 MB
__device__ float g_h[MROWS*FFNDIM];      // 256 MB

__device__ __forceinline__ float gelu_exact(float v) {
    return 0.5f * v * (1.0f + erff(v * 0.70710678118654752f));
}

__device__ __forceinline__ uint32_t smem_u32(const void* p) {
    uint32_t a;
    asm("{ .reg .u64 t; cvta.to.shared.u64 t, %1; cvt.u32.u64 %0, t; }"
        : "=r"(a) : "l"(p));
    return a;
}

// ---- packed f32x2 helpers (Blackwell base ISA, PTX 8.6, sm_100+) ----------
__device__ __forceinline__ uint64_t pk2(float x, float y) {
    uint64_t r;
    asm("mov.b64 %0, {%1, %2};" : "=l"(r) : "f"(x), "f"(y));
    return r;
}
__device__ __forceinline__ void upk2(uint64_t v, float& x, float& y) {
    asm("mov.b64 {%0, %1}, %2;" : "=f"(x), "=f"(y) : "l"(v));
}
__device__ __forceinline__ uint64_t fma2(uint64_t a, uint64_t b, uint64_t c) {
    uint64_t d;
    asm("fma.rn.f32x2 %0, %1, %2, %3;" : "=l"(d) : "l"(a), "l"(b), "l"(c));
    return d;
}

__device__ __forceinline__ void ldsm4(uint32_t addr, uint32_t r[4]) {
    asm volatile("ldmatrix.sync.aligned.m8n8.x4.shared.b16 {%0,%1,%2,%3}, [%4];"
                 : "=r"(r[0]), "=r"(r[1]), "=r"(r[2]), "=r"(r[3]) : "r"(addr));
}

__device__ __forceinline__ void mma16816(float c[4], const uint32_t a[4],
                                         uint32_t b0, uint32_t b1) {
    asm volatile(
        "mma.sync.aligned.m16n8k16.row.col.f32.f16.f16.f32 "
        "{%0,%1,%2,%3}, {%4,%5,%6,%7}, {%8,%9}, {%0,%1,%2,%3};"
        : "+f"(c[0]), "+f"(c[1]), "+f"(c[2]), "+f"(c[3])
        : "r"(a[0]), "r"(a[1]), "r"(a[2]), "r"(a[3]), "r"(b0), "r"(b1));
}

// ---------------------------------------------------------------------------
// fp16-split (3-pass) tensor-core GEMM:
//   C[M,N] = A[M,K] @ B[N,K]^T  (+bias[n]) (gelu) (+add1) (+add2)
// Block tile 128x128, 8 warps of 32x64, K-chunks of 32, double-buffered SMEM.
// ---------------------------------------------------------------------------
#define GH_STRIDE_B 80
#define GH_TILE_B   (128 * GH_STRIDE_B)
#define GH_AB 0
#define GH_AS (1 * GH_TILE_B)
#define GH_BB (2 * GH_TILE_B)
#define GH_BS (3 * GH_TILE_B)
#define GH_STAGE (4 * GH_TILE_B)
#define GH_DYN_SMEM (2 * GH_STAGE)

__global__ void __launch_bounds__(256, 1) gemm_h3_kernel(
    const float* __restrict__ A, const float* __restrict__ B,
    float* __restrict__ Cmat,
    int M, int N, int K,
    const float* __restrict__ bias, const float* __restrict__ add1,
    const float* __restrict__ add2, int do_gelu)
{
    extern __shared__ char smem[];
    const uint32_t sbase = smem_u32(smem);

    const int tid = threadIdx.x;
    const int w   = tid >> 5;
    const int l   = tid & 31;

    const size_t row0 = (size_t)blockIdx.y * 128;
    const size_t col0 = (size_t)blockIdx.x * 128;
    const int Kc = K >> 5;

    const int rbase = tid >> 3;
    const int c4    = tid & 7;
    const float* Ap = A + (row0 + rbase) * (size_t)K + c4 * 4;
    const float* Bp = B + (col0 + rbase) * (size_t)K + c4 * 4;

    float4 ra[4], rb4[4];
#pragma unroll
    for (int i = 0; i < 4; ++i) {
        ra[i]  = *(const float4*)(Ap + (size_t)(32 * i) * K);
        rb4[i] = *(const float4*)(Bp + (size_t)(32 * i) * K);
    }

    const uint32_t stoff = (uint32_t)rbase * GH_STRIDE_B + (uint32_t)c4 * 8;

#define CVST(sidx)                                                             \
    do {                                                                       \
        char* pAb = smem + (sidx) * GH_STAGE + GH_AB;                          \
        char* pAs = smem + (sidx) * GH_STAGE + GH_AS;                          \
        char* pBb = smem + (sidx) * GH_STAGE + GH_BB;                          \
        char* pBs = smem + (sidx) * GH_STAGE + GH_BS;                          \
        _Pragma("unroll")                                                      \
        for (int i = 0; i < 4; ++i) {                                          \
            uint32_t off = stoff + (uint32_t)i * (32u * GH_STRIDE_B);          \
            union { __half2 h2[2]; uint2 u; } pk;                              \
            __half2 hb0 = __floats2half2_rn(ra[i].x, ra[i].y);                 \
            __half2 hb1 = __floats2half2_rn(ra[i].z, ra[i].w);                 \
            float2 f0 = __half22float2(hb0), f1 = __half22float2(hb1);         \
            pk.h2[0] = hb0; pk.h2[1] = hb1;                                    \
            *(uint2*)(pAb + off) = pk.u;                                       \
            pk.h2[0] = __floats2half2_rn(ra[i].x - f0.x, ra[i].y - f0.y);      \
            pk.h2[1] = __floats2half2_rn(ra[i].z - f1.x, ra[i].w - f1.y);      \
            *(uint2*)(pAs + off) = pk.u;                                       \
            hb0 = __floats2half2_rn(rb4[i].x, rb4[i].y);                       \
            hb1 = __floats2half2_rn(rb4[i].z, rb4[i].w);                       \
            f0 = __half22float2(hb0); f1 = __half22float2(hb1);                \
            pk.h2[0] = hb0; pk.h2[1] = hb1;                                    \
            *(uint2*)(pBb + off) = pk.u;                                       \
            pk.h2[0] = __floats2half2_rn(rb4[i].x - f0.x, rb4[i].y - f0.y);    \
            pk.h2[1] = __floats2half2_rn(rb4[i].z - f1.x, rb4[i].w - f1.y);    \
            *(uint2*)(pBs + off) = pk.u;                                       \
        }                                                                      \
    } while (0)

    CVST(0);
    __syncthreads();

    const int m0 = (w & 3) * 32;
    const int n0 = (w >> 2) * 64;
    const int rA = l & 15;
    const int qA = l >> 4;
    const int rB = (l & 7) | ((l & 16) >> 1);
    const int qB = (l >> 3) & 1;

    float acc[2][8][4];
#pragma unroll
    for (int mi = 0; mi < 2; ++mi)
#pragma unroll
        for (int ni = 0; ni < 8; ++ni)
#pragma unroll
            for (int q = 0; q < 4; ++q) acc[mi][ni][q] = 0.f;

    for (int kt = 0; kt < Kc; ++kt) {
        if (kt + 1 < Kc) {
            const float* Ap2 = Ap + (kt + 1) * 32;
            const float* Bp2 = Bp + (kt + 1) * 32;
#pragma unroll
            for (int i = 0; i < 4; ++i) {
                ra[i]  = *(const float4*)(Ap2 + (size_t)(32 * i) * K);
                rb4[i] = *(const float4*)(Bp2 + (size_t)(32 * i) * K);
            }
        }

        const uint32_t stb = sbase + (uint32_t)(kt & 1) * GH_STAGE;
#pragma unroll
        for (int kk = 0; kk < 2; ++kk) {
            const int q0 = kk * 2;
            uint32_t ab[2][4], as2[2][4], bb[4][4];
            const uint32_t aoff =
                (uint32_t)(m0 + rA) * GH_STRIDE_B + (uint32_t)(q0 + qA) * 16;
            const uint32_t boff =
                (uint32_t)(n0 + rB) * GH_STRIDE_B + (uint32_t)(q0 + qB) * 16;

            ldsm4(stb + GH_AB + aoff, ab[0]);
            ldsm4(stb + GH_AB + aoff + 16u * GH_STRIDE_B, ab[1]);
            ldsm4(stb + GH_AS + aoff, as2[0]);
            ldsm4(stb + GH_AS + aoff + 16u * GH_STRIDE_B, as2[1]);
#pragma unroll
            for (int g = 0; g < 4; ++g)
                ldsm4(stb + GH_BB + boff + (uint32_t)g * (16u * GH_STRIDE_B), bb[g]);

#pragma unroll
            for (int mi = 0; mi < 2; ++mi)
#pragma unroll
                for (int g = 0; g < 4; ++g) {
                    mma16816(acc[mi][2 * g],     ab[mi], bb[g][0], bb[g][1]);
                    mma16816(acc[mi][2 * g + 1], ab[mi], bb[g][2], bb[g][3]);
                }
#pragma unroll
            for (int mi = 0; mi < 2; ++mi)
#pragma unroll
                for (int g = 0; g < 4; ++g) {
                    mma16816(acc[mi][2 * g],     as2[mi], bb[g][0], bb[g][1]);
                    mma16816(acc[mi][2 * g + 1], as2[mi], bb[g][2], bb[g][3]);
                }
#pragma unroll
            for (int g = 0; g < 4; ++g)
                ldsm4(stb + GH_BS + boff + (uint32_t)g * (16u * GH_STRIDE_B), bb[g]);
#pragma unroll
            for (int mi = 0; mi < 2; ++mi)
#pragma unroll
                for (int g = 0; g < 4; ++g) {
                    mma16816(acc[mi][2 * g],     ab[mi], bb[g][0], bb[g][1]);
                    mma16816(acc[mi][2 * g + 1], ab[mi], bb[g][2], bb[g][3]);
                }
        }

        if (kt + 1 < Kc) CVST((kt + 1) & 1);
        __syncthreads();
    }
#undef CVST

#pragma unroll
    for (int mi = 0; mi < 2; ++mi) {
        const size_t rtop = row0 + m0 + mi * 16 + (l >> 2);
#pragma unroll
        for (int ni = 0; ni < 8; ++ni) {
            const int gc = (int)col0 + n0 + ni * 8 + (l & 3) * 2;
            float bx = 0.f, by = 0.f;
            if (bias) {
                float2 bb2 = *(const float2*)(bias + gc);
                bx = bb2.x; by = bb2.y;
            }
#pragma unroll
            for (int h = 0; h < 2; ++h) {
                const size_t r = rtop + h * 8;
                float vx = acc[mi][ni][h * 2 + 0] + bx;
                float vy = acc[mi][ni][h * 2 + 1] + by;
                if (do_gelu) { vx = gelu_exact(vx); vy = gelu_exact(vy); }
                const size_t idx = r * (size_t)N + gc;
                if (add1) {
                    float2 t = *(const float2*)(add1 + idx);
                    vx += t.x; vy += t.y;
                }
                if (add2) {
                    float2 t = *(const float2*)(add2 + idx);
                    vx += t.x; vy += t.y;
                }
                float2 o; o.x = vx; o.y = vy;
                *(float2*)(Cmat + idx) = o;
            }
        }
    }
}

// ---------------------------------------------------------------------------
// Sequential scan v2: 8 blocks x 1024 threads, one block per batch.
//   thread = (i = tid&255 output row, jg = tid>>8 k-quarter of 64)
//   A: 40 coeffs in registers (20 f32x2 pairs) + 24 via column-major SMEM
//   state reads: LDS.128 broadcasts (warp-uniform jg)
//   math: fma.rn.f32x2 packed fp32
// SMEM: Asm float4[24][256] (96KB) | st float[256] | part float[1024] |
//       xb float[2][256]
// ---------------------------------------------------------------------------
#define SC_ASM_BYTES (24 * 256 * 16)
#define SC_SMEM_BYTES (SC_ASM_BYTES + (256 + 1024 + 512) * 4)

__global__ void __launch_bounds__(1024, 1) scan2_kernel(
    const float* __restrict__ Amat,
    const float* __restrict__ xB,
    float* __restrict__ states,
    float* __restrict__ fs_out)
{
    extern __shared__ char ssm[];
    float4* Asm  = (float4*)ssm;                        // [24][256]
    float*  stf  = (float*)(ssm + SC_ASM_BYTES);        // [256]
    float*  part = stf + 256;                           // [1024]
    float*  xb   = part + 1024;                         // [2][256]

    const int tid = threadIdx.x;
    const int i   = tid & 255;
    const int jg  = tid >> 8;
    const int b   = blockIdx.x;

    // Load A row slice: k in [64*jg, 64*jg+64)
    const float* arow = Amat + i * STATE + jg * 64;
    uint64_t areg[20];
#pragma unroll
    for (int q = 0; q < 10; ++q) {
        float4 a4 = *(const float4*)(arow + 4 * q);
        areg[2 * q]     = pk2(a4.x, a4.y);
        areg[2 * q + 1] = pk2(a4.z, a4.w);
    }
#pragma unroll
    for (int q = 10; q < 16; ++q)
        Asm[(jg * 6 + (q - 10)) * 256 + i] = *(const float4*)(arow + 4 * q);

    const float* xbbase = xB + (size_t)b * TLEN * STATE;
    float* sbptr = states + (size_t)b * TLEN * STATE;

    if (tid < STATE) {
        stf[tid] = 0.f;
        xb[tid]  = xbbase[tid];
    }
    __syncthreads();

    const float4* st4 = (const float4*)stf;
    const int q16 = jg * 16;
    const int asmbase = jg * 6 * 256 + i;

    for (int t = 0; t < TLEN; ++t) {
        float pref = 0.f;
        if (tid < STATE && t + 1 < TLEN)
            pref = xbbase[(size_t)(t + 1) * STATE + tid];

        uint64_t acc0 = pk2(0.f, 0.f);
        uint64_t acc1 = pk2(0.f, 0.f);
#pragma unroll
        for (int q = 0; q < 10; ++q) {
            float4 s4 = st4[q16 + q];
            acc0 = fma2(areg[2 * q],     pk2(s4.x, s4.y), acc0);
            acc1 = fma2(areg[2 * q + 1], pk2(s4.z, s4.w), acc1);
        }
#pragma unroll
        for (int q = 10; q < 16; ++q) {
            float4 s4 = st4[q16 + q];
            float4 a4 = Asm[asmbase + (q - 10) * 256];
            acc0 = fma2(pk2(a4.x, a4.y), pk2(s4.x, s4.y), acc0);
            acc1 = fma2(pk2(a4.z, a4.w), pk2(s4.z, s4.w), acc1);
        }
        float l0, h0, l1, h1;
        upk2(acc0, l0, h0);
        upk2(acc1, l1, h1);
        part[jg * 256 + i] = (l0 + h0) + (l1 + h1);
        __syncthreads();

        if (tid < STATE) {
            float v = part[tid] + part[256 + tid] + part[512 + tid] +
                      part[768 + tid] + xb[(t & 1) * 256 + tid];
            float ax = fabsf(v);
            float e  = __expf(2.0f * ax);
            float tt = copysignf(1.0f - __fdividef(2.0f, e + 1.0f), v);
            stf[tid] = tt;
            sbptr[(size_t)t * STATE + tid] = tt;
            xb[((t & 1) ^ 1) * 256 + tid] = pref;
        }
        __syncthreads();
    }

    if (fs_out != nullptr && tid < STATE)
        fs_out[b * STATE + tid] = stf[tid];
}

// ---------------------------------------------------------------------------
// LayerNorm over last dim (1024). One block per row, 256 threads x float4.
// ---------------------------------------------------------------------------
__global__ void __launch_bounds__(256) ln_kernel(
    const float* __restrict__ R, const float* __restrict__ w,
    const float* __restrict__ b, float* __restrict__ Y)
{
    const int row = blockIdx.x;
    const int tid = threadIdx.x;
    const float4 v = ((const float4*)(R + (size_t)row * HID))[tid];

    float s  = v.x + v.y + v.z + v.w;
    float sq = v.x * v.x + v.y * v.y + v.z * v.z + v.w * v.w;
#pragma unroll
    for (int o = 16; o; o >>= 1) {
        s  += __shfl_xor_sync(0xffffffffu, s, o);
        sq += __shfl_xor_sync(0xffffffffu, sq, o);
    }
    __shared__ float ss[8], sqq[8], mv[2];
    const int wid = tid >> 5, lane = tid & 31;
    if (lane == 0) { ss[wid] = s; sqq[wid] = sq; }
    __syncthreads();
    if (tid == 0) {
        float S = 0.f, Q = 0.f;
#pragma unroll
        for (int k = 0; k < 8; ++k) { S += ss[k]; Q += sqq[k]; }
        float mu  = S * (1.0f / HID);
        float var = Q * (1.0f / HID) - mu * mu;
        mv[0] = mu;
        mv[1] = rsqrtf(var + 1e-5f);
    }
    __syncthreads();
    const float mu = mv[0], inv = mv[1];
    const float4 w4 = ((const float4*)w)[tid];
    const float4 b4 = ((const float4*)b)[tid];
    float4 o;
    o.x = (v.x - mu) * inv * w4.x + b4.x;
    o.y = (v.y - mu) * inv * w4.y + b4.y;
    o.z = (v.z - mu) * inv * w4.z + b4.z;
    o.w = (v.w - mu) * inv * w4.w + b4.w;
    ((float4*)(Y + (size_t)row * HID))[tid] = o;
}

// ---------------------------------------------------------------------------
// Launch
// ---------------------------------------------------------------------------
extern "C" void kernel_launch(void* const* d_in, const int* in_sizes, int n_in,
                              void* d_out, int out_size)
{
    const float* x    = (const float*)d_in[0];
    const float* Amat = (const float*)d_in[1];
    const float* Bm   = (const float*)d_in[2];
    const float* Cm   = (const float*)d_in[3];
    const float* D    = (const float*)d_in[4];
    const float* ln_w = (const float*)d_in[5];
    const float* ln_b = (const float*)d_in[6];
    const float* W1   = (const float*)d_in[7];
    const float* b1   = (const float*)d_in[8];
    const float* W2   = (const float*)d_in[9];
    const float* b2   = (const float*)d_in[10];
    float* out = (float*)d_out;

    float *xB, *xD, *states, *yln, *h;
    cudaGetSymbolAddress((void**)&xB,     g_xB);
    cudaGetSymbolAddress((void**)&xD,     g_xD);
    cudaGetSymbolAddress((void**)&states, g_states);
    cudaGetSymbolAddress((void**)&yln,    g_yln);
    cudaGetSymbolAddress((void**)&h,      g_h);

    cudaFuncSetAttribute(scan2_kernel,
                         cudaFuncAttributeMaxDynamicSharedMemorySize,
                         SC_SMEM_BYTES);
    cudaFuncSetAttribute(gemm_h3_kernel,
                         cudaFuncAttributeMaxDynamicSharedMemorySize,
                         GH_DYN_SMEM);

    const int M = MROWS;

    // 1) xB = x @ Bm^T
    gemm_h3_kernel<<<dim3(STATE / 128, M / 128), 256, GH_DYN_SMEM>>>(
        x, Bm, xB, M, STATE, HID, nullptr, nullptr, nullptr, 0);

    // 2) xD = x @ D^T
    gemm_h3_kernel<<<dim3(HID / 128, M / 128), 256, GH_DYN_SMEM>>>(
        x, D, xD, M, HID, HID, nullptr, nullptr, nullptr, 0);

    // 3) sequential scan -> states (+ final_state into tail of d_out)
    float* fsp = (out_size >= MROWS * HID + BSZ * STATE)
                     ? (out + (size_t)MROWS * HID) : nullptr;
    scan2_kernel<<<BSZ, 1024, SC_SMEM_BYTES>>>(Amat, xB, states, fsp);

    // 4) r = states @ C^T + xD + x  (in-place into xD)
    gemm_h3_kernel<<<dim3(HID / 128, M / 128), 256, GH_DYN_SMEM>>>(
        states, Cm, xD, M, HID, STATE, nullptr, xD, x, 0);

    // 5) yln = LayerNorm(r)
    ln_kernel<<<M, 256>>>(xD, ln_w, ln_b, yln);

    // 6) h = gelu(yln @ W1^T + b1)
    gemm_h3_kernel<<<dim3(FFNDIM / 128, M / 128), 256, GH_DYN_SMEM>>>(
        yln, W1, h, M, FFNDIM, HID, b1, nullptr, nullptr, 1);

    // 7) y = yln + h @ W2^T + b2 -> d_out
    gemm_h3_kernel<<<dim3(HID / 128, M / 128), 256, GH_DYN_SMEM>>>(
        h, W2, out, M, HID, FFNDIM, b2, yln, nullptr, 0);
}